// round 1
// baseline (speedup 1.0000x reference)
#include <cuda_runtime.h>

#define Hh 720
#define Ww 1440
#define BW 10
#define TH 16
#define TW 160
#define SXW (TW + 4)      // 164
#define NTHREADS 256

__global__ __launch_bounds__(NTHREADS)
void seg_smooth_kernel(const float* __restrict__ x, float* __restrict__ out)
{
    __shared__ float sx [TH + 4][SXW];  // raw tile + halo
    __shared__ float shS[TH + 4][TW];   // horizontal 5-sums (all pixels)
    __shared__ float shB[TH + 4][TW];   // horizontal 5-sums of boundary-class pixels

    const int gj0   = blockIdx.x * TW;
    const int gi0   = blockIdx.y * TH;
    const int plane = blockIdx.z;
    const float* __restrict__ xp = x   + (size_t)plane * (Hh * Ww);
    float* __restrict__       op = out + (size_t)plane * (Hh * Ww);
    const int tid = threadIdx.x;

    // Tile is "pure" if no output window in it touches a boundary-class pixel
    // (which also implies no window clipping): out = boxsum(x)/25 everywhere.
    const bool pure = (gi0 >= BW + 2) && (gi0 + TH <= Hh - BW - 2) &&
                      (gj0 >= BW + 2) && (gj0 + TW <= Ww - BW - 2);

    // ---- Phase 1: stage tile + 2-halo into SMEM (zero-fill = SAME padding) ----
    #pragma unroll 4
    for (int idx = tid; idx < (TH + 4) * SXW; idx += NTHREADS) {
        const int r  = idx / SXW;
        const int c  = idx - r * SXW;
        const int gi = gi0 - 2 + r;
        const int gj = gj0 - 2 + c;
        float v = 0.0f;
        if (gi >= 0 && gi < Hh && gj >= 0 && gj < Ww)
            v = xp[gi * Ww + gj];
        sx[r][c] = v;
    }
    __syncthreads();

    // ---- Phase 2: horizontal 5-sums ----
    #pragma unroll 2
    for (int idx = tid; idx < (TH + 4) * TW; idx += NTHREADS) {
        const int r = idx / TW;
        const int c = idx - r * TW;
        const float a0 = sx[r][c    ];
        const float a1 = sx[r][c + 1];
        const float a2 = sx[r][c + 2];
        const float a3 = sx[r][c + 3];
        const float a4 = sx[r][c + 4];
        const float hs = ((a0 + a1) + (a2 + a3)) + a4;
        shS[r][c] = hs;
        if (!pure) {
            const int gi = gi0 - 2 + r;
            const int gj = gj0 + c;                 // output column for this sum
            const bool rb = (gi < BW) || (gi >= Hh - BW);
            float hb;
            if (rb) {
                hb = hs;                            // whole row is boundary class
            } else {
                hb = 0.0f;
                #pragma unroll
                for (int dc = 0; dc < 5; ++dc) {
                    const int jj = gj - 2 + dc;
                    if (jj < BW || jj >= Ww - BW)   // OOB jj<0 loads sx==0: harmless
                        hb += sx[r][c + dc];
                }
            }
            shB[r][c] = hb;
        }
    }
    __syncthreads();

    // ---- Phase 3: vertical 5-sums + analytic counts + select ----
    if (pure) {
        #pragma unroll 2
        for (int idx = tid; idx < TH * TW; idx += NTHREADS) {
            const int rr = idx / TW;
            const int c  = idx - rr * TW;
            const float s = ((shS[rr][c] + shS[rr + 1][c]) +
                             (shS[rr + 2][c] + shS[rr + 3][c])) + shS[rr + 4][c];
            op[(gi0 + rr) * Ww + gj0 + c] = s * 0.04f;
        }
    } else {
        for (int idx = tid; idx < TH * TW; idx += NTHREADS) {
            const int rr = idx / TW;
            const int c  = idx - rr * TW;
            const int i  = gi0 + rr;
            const int j  = gj0 + c;

            const float S  = ((shS[rr][c] + shS[rr + 1][c]) +
                              (shS[rr + 2][c] + shS[rr + 3][c])) + shS[rr + 4][c];
            const float NB = ((shB[rr][c] + shB[rr + 1][c]) +
                              (shB[rr + 2][c] + shB[rr + 3][c])) + shB[rr + 4][c];

            // Analytic in-range window counts (reference's zero-padded count sums)
            const int r0 = max(i - 2, 0), r1 = min(i + 2, Hh - 1);
            const int c0 = max(j - 2, 0), c1 = min(j + 2, Ww - 1);
            const int nrows = r1 - r0 + 1;
            const int ncols = c1 - c0 + 1;
            const int nbr = max(0, min(r1, BW - 1) - r0 + 1) +
                            max(0, r1 - max(r0, Hh - BW) + 1);
            const int nbc = max(0, min(c1, BW - 1) - c0 + 1) +
                            max(0, c1 - max(c0, Ww - BW) + 1);
            const int cntB = nbr * ncols + (nrows - nbr) * nbc;

            const bool mbp = (i < BW) || (i >= Hh - BW) || (j < BW) || (j >= Ww - BW);
            float num, cnt;
            if (mbp) { num = NB;     cnt = (float)cntB; }
            else     { num = S - NB; cnt = (float)(nrows * ncols - cntB); }

            op[i * Ww + j] = num / cnt;
        }
    }
}

extern "C" void kernel_launch(void* const* d_in, const int* in_sizes, int n_in,
                              void* d_out, int out_size)
{
    const float* x = (const float*)d_in[0];
    float* out = (float*)d_out;
    const int planes = out_size / (Hh * Ww);   // 4*16 = 64
    dim3 grid(Ww / TW, Hh / TH, planes);       // 9 x 45 x 64
    seg_smooth_kernel<<<grid, NTHREADS>>>(x, out);
}

// round 2
// speedup vs baseline: 1.3637x; 1.3637x over previous
#include <cuda_runtime.h>

#define Hh 720
#define Ww 1440
#define BW 10
#define RSTRIP 20          // output rows per block strip (720 = 36 * 20)
#define NTH 384            // 354 pure-column threads + 6 frame threads + idle

__device__ __forceinline__ float4 f4add(const float4 a, const float4 b) {
    return make_float4(a.x + b.x, a.y + b.y, a.z + b.z, a.w + b.w);
}
__device__ __forceinline__ float4 f4sub(const float4 a, const float4 b) {
    return make_float4(a.x - b.x, a.y - b.y, a.z - b.z, a.w - b.w);
}
__device__ __forceinline__ float4 f4scale(const float4 a, const float s) {
    return make_float4(a.x * s, a.y * s, a.z * s, a.w * s);
}

// Horizontal 5-sums for 4 outputs at cols cb+4..cb+7, reading cols cb..cb+11.
// Requires cb >= 0 and cb+11 < Ww (true for all pure-column threads).
__device__ __forceinline__ float4 hrow_pure(const float* __restrict__ xp, int r, int cb)
{
    float4 h;
    if ((unsigned)r < (unsigned)Hh) {
        const float4* p = reinterpret_cast<const float4*>(xp + (size_t)r * Ww + cb);
        const float4 A = p[0];
        const float4 B = p[1];
        const float4 C = p[2];
        h.x = ((A.z + A.w) + (B.x + B.y)) + B.z;
        h.y = h.x - A.z + B.w;
        h.z = h.y - A.w + C.x;
        h.w = h.z - B.x + C.y;
    } else {
        h = make_float4(0.f, 0.f, 0.f, 0.f);
    }
    return h;
}

__global__ __launch_bounds__(NTH, 3)
void seg_smooth_main(const float* __restrict__ x, float* __restrict__ out)
{
    const int tid   = threadIdx.x;
    const int gi0   = blockIdx.x * RSTRIP;
    const int plane = blockIdx.y;
    const float* __restrict__ xp = x   + (size_t)plane * (Hh * Ww);
    float* __restrict__       op = out + (size_t)plane * (Hh * Ww);

    if (tid < 354) {
        // ============ pure-column rolling path (cols 12..1427) ============
        // Every window column is interior-class: boundary contributions come
        // only from boundary ROWS, i.e. masked sums of the hS ring itself.
        const int g  = tid + 3;              // column group, cols 4g..4g+3
        const int cb = 4 * g - 4;            // leftmost loaded col (>= 8)

        float4 h[5];
        h[0] = hrow_pure(xp, gi0 - 2, cb);
        h[1] = hrow_pure(xp, gi0 - 1, cb);
        h[2] = hrow_pure(xp, gi0    , cb);
        h[3] = hrow_pure(xp, gi0 + 1, cb);
        h[4] = make_float4(0.f, 0.f, 0.f, 0.f);
        float4 acc = f4add(f4add(h[0], h[1]), f4add(h[2], h[3]));

        #pragma unroll 1
        for (int a = 0; a < RSTRIP / 5; ++a) {
            #pragma unroll
            for (int b = 0; b < 5; ++b) {
                const int rr = a * 5 + b;
                const int i  = gi0 + rr;
                const int sn = (b + 4) % 5;              // static slot
                h[sn] = hrow_pure(xp, i + 2, cb);
                const float4 S = f4add(acc, h[sn]);
                float4 o;
                if (i >= BW + 2 && i < Hh - BW - 2) {
                    o = f4scale(S, 0.04f);               // all-interior window
                } else {
                    // masked vertical sum over boundary-class rows
                    float4 NB = make_float4(0.f, 0.f, 0.f, 0.f);
                    #pragma unroll
                    for (int k = 0; k < 5; ++k) {
                        const int rk = i - 2 + k;        // OOB rows: h == 0
                        if (rk < BW || rk >= Hh - BW)
                            NB = f4add(NB, h[(b + k) % 5]);
                    }
                    const int r0 = max(i - 2, 0), r1 = min(i + 2, Hh - 1);
                    const int nrows = r1 - r0 + 1;
                    const int nbr = max(0, min(r1, BW - 1) - r0 + 1)
                                  + max(0, r1 - max(r0, Hh - BW) + 1);
                    if (i < BW || i >= Hh - BW) {
                        o = f4scale(NB, 1.0f / (float)(5 * nbr));
                    } else {
                        o = f4scale(f4sub(S, NB),
                                    1.0f / (float)(5 * (nrows - nbr)));
                    }
                }
                reinterpret_cast<float4*>(op + (size_t)i * Ww + (cb + 4))[0] = o;
                acc = f4sub(S, h[b]);                    // drop row i-2
            }
        }
    } else if (tid < 360) {
        // ============ frame-column naive path (cols 0..11, 1428..1439) ====
        const int t  = tid - 354;
        const int g  = (t < 3) ? t : (t + 354);          // {0,1,2,357,358,359}
        const int cb = 4 * g - 4;
        const bool Aok = (cb >= 0);
        const bool Cok = (cb + 11 < Ww);

        // boundary-class multipliers for the 8 window cols cb+2..cb+9
        float m[8];
        #pragma unroll
        for (int c = 0; c < 8; ++c) {
            const int col = cb + 2 + c;
            m[c] = (col < BW || col >= Ww - BW) ? 1.0f : 0.0f;
        }
        // per-output-col analytic count pieces
        int ncols[4], nbc[4];
        bool colB[4];
        #pragma unroll
        for (int c = 0; c < 4; ++c) {
            const int j  = cb + 4 + c;
            const int c0 = max(j - 2, 0), c1 = min(j + 2, Ww - 1);
            ncols[c] = c1 - c0 + 1;
            nbc[c]   = max(0, min(c1, BW - 1) - c0 + 1)
                     + max(0, c1 - max(c0, Ww - BW) + 1);
            colB[c]  = (j < BW || j >= Ww - BW);
        }

        for (int rr = 0; rr < RSTRIP; ++rr) {
            const int i = gi0 + rr;
            float4 S  = make_float4(0.f, 0.f, 0.f, 0.f);
            float4 NB = make_float4(0.f, 0.f, 0.f, 0.f);
            #pragma unroll
            for (int k = 0; k < 5; ++k) {
                const int r = i - 2 + k;
                if ((unsigned)r < (unsigned)Hh) {
                    const float* rowp = xp + (size_t)r * Ww;
                    const float4 A = Aok ? reinterpret_cast<const float4*>(rowp + cb)[0]
                                         : make_float4(0.f, 0.f, 0.f, 0.f);
                    const float4 B = reinterpret_cast<const float4*>(rowp + cb + 4)[0];
                    const float4 C = Cok ? reinterpret_cast<const float4*>(rowp + cb + 8)[0]
                                         : make_float4(0.f, 0.f, 0.f, 0.f);
                    float4 h;
                    h.x = ((A.z + A.w) + (B.x + B.y)) + B.z;
                    h.y = h.x - A.z + B.w;
                    h.z = h.y - A.w + C.x;
                    h.w = h.z - B.x + C.y;
                    S = f4add(S, h);
                    if (r < BW || r >= Hh - BW) {
                        NB = f4add(NB, h);               // whole row boundary
                    } else {
                        const float w0 = A.z * m[0], w1 = A.w * m[1];
                        const float w2 = B.x * m[2], w3 = B.y * m[3];
                        const float w4 = B.z * m[4], w5 = B.w * m[5];
                        const float w6 = C.x * m[6], w7 = C.y * m[7];
                        float4 hb;
                        hb.x = ((w0 + w1) + (w2 + w3)) + w4;
                        hb.y = hb.x - w0 + w5;
                        hb.z = hb.y - w1 + w6;
                        hb.w = hb.z - w2 + w7;
                        NB = f4add(NB, hb);
                    }
                }
            }
            const int r0 = max(i - 2, 0), r1 = min(i + 2, Hh - 1);
            const int nrows = r1 - r0 + 1;
            const int nbr = max(0, min(r1, BW - 1) - r0 + 1)
                          + max(0, r1 - max(r0, Hh - BW) + 1);
            const bool rowBi = (i < BW || i >= Hh - BW);
            const float sv[4]  = {S.x, S.y, S.z, S.w};
            const float nbv[4] = {NB.x, NB.y, NB.z, NB.w};
            float ov[4];
            #pragma unroll
            for (int c = 0; c < 4; ++c) {
                const int  cntB = nbr * ncols[c] + (nrows - nbr) * nbc[c];
                const bool mb   = rowBi || colB[c];
                const float num = mb ? nbv[c] : (sv[c] - nbv[c]);
                const int   cnt = mb ? cntB : (nrows * ncols[c] - cntB);
                ov[c] = num / (float)cnt;
            }
            reinterpret_cast<float4*>(op + (size_t)i * Ww + (cb + 4))[0]
                = make_float4(ov[0], ov[1], ov[2], ov[3]);
        }
    }
}

extern "C" void kernel_launch(void* const* d_in, const int* in_sizes, int n_in,
                              void* d_out, int out_size)
{
    const float* x = (const float*)d_in[0];
    float* out = (float*)d_out;
    const int planes = out_size / (Hh * Ww);   // 64
    dim3 grid(Hh / RSTRIP, planes);            // 36 x 64 = 2304 blocks
    seg_smooth_main<<<grid, NTH>>>(x, out);
}

// round 3
// speedup vs baseline: 1.8953x; 1.3898x over previous
#include <cuda_runtime.h>

#define Hh 720
#define Ww 1440
#define BW 10
#define RSTRIP 20          // output rows per strip (720 = 36 * 20)

__device__ __forceinline__ float4 f4add(const float4 a, const float4 b) {
    return make_float4(a.x + b.x, a.y + b.y, a.z + b.z, a.w + b.w);
}
__device__ __forceinline__ float4 f4sub(const float4 a, const float4 b) {
    return make_float4(a.x - b.x, a.y - b.y, a.z - b.z, a.w - b.w);
}
__device__ __forceinline__ float4 f4scale(const float4 a, const float s) {
    return make_float4(a.x * s, a.y * s, a.z * s, a.w * s);
}

// Load 3 aligned float4 covering cols cb..cb+11 of row r (zero-fill OOB rows).
__device__ __forceinline__ void loadraw(const float* __restrict__ xp, int r, int cb,
                                        float4& A, float4& B, float4& C)
{
    if ((unsigned)r < (unsigned)Hh) {
        const float4* p = reinterpret_cast<const float4*>(xp + (size_t)r * Ww + cb);
        A = p[0]; B = p[1]; C = p[2];
    } else {
        A = B = C = make_float4(0.f, 0.f, 0.f, 0.f);
    }
}

__device__ __forceinline__ float4 hfrom(const float4 A, const float4 B, const float4 C)
{
    float4 h;
    h.x = ((A.z + A.w) + (B.x + B.y)) + B.z;
    h.y = h.x - A.z + B.w;
    h.z = h.y - A.w + C.x;
    h.w = h.z - B.x + C.y;
    return h;
}

// ===================== main kernel: pure columns 12..1427 =====================
// Column groups g in [3, 356]: every window column is interior-class, so the
// boundary-class numerator is a row-masked sum of the h ring itself.
__global__ __launch_bounds__(128, 8)
void seg_pure(const float* __restrict__ x, float* __restrict__ out)
{
    const int g = blockIdx.x * 128 + threadIdx.x;
    if (g < 3 || g > 356) return;
    const int cb    = 4 * g - 4;
    const int gi0   = blockIdx.y * RSTRIP;
    const int plane = blockIdx.z;
    const float* __restrict__ xp = x   + (size_t)plane * (Hh * Ww);
    float* __restrict__       op = out + (size_t)plane * (Hh * Ww);

    // ring of horizontal 5-sums for rows gi0-2 .. gi0+1
    float4 h[5];
    {
        float4 A, B, C;
        loadraw(xp, gi0 - 2, cb, A, B, C); h[0] = hfrom(A, B, C);
        loadraw(xp, gi0 - 1, cb, A, B, C); h[1] = hfrom(A, B, C);
        loadraw(xp, gi0    , cb, A, B, C); h[2] = hfrom(A, B, C);
        loadraw(xp, gi0 + 1, cb, A, B, C); h[3] = hfrom(A, B, C);
    }
    float4 acc = f4add(f4add(h[0], h[1]), f4add(h[2], h[3]));

    // prefetch raw data for row gi0+2
    float4 A, B, C;
    loadraw(xp, gi0 + 2, cb, A, B, C);

    #pragma unroll 1
    for (int a = 0; a < RSTRIP / 5; ++a) {
        #pragma unroll
        for (int b = 0; b < 5; ++b) {
            const int rr = a * 5 + b;
            const int i  = gi0 + rr;

            const float4 hn = hfrom(A, B, C);        // h of row i+2 (prefetched)
            if (rr < RSTRIP - 1)
                loadraw(xp, i + 3, cb, A, B, C);     // prefetch next row

            const int sn = (b + 4) % 5;
            h[sn] = hn;
            const float4 S = f4add(acc, hn);

            float4 o;
            if (i >= BW + 2 && i < Hh - BW - 2) {
                o = f4scale(S, 0.04f);
            } else {
                float4 NB = make_float4(0.f, 0.f, 0.f, 0.f);
                #pragma unroll
                for (int k = 0; k < 5; ++k) {
                    const int rk = i - 2 + k;        // OOB rows: h == 0
                    if (rk < BW || rk >= Hh - BW)
                        NB = f4add(NB, h[(b + k) % 5]);
                }
                const int r0 = max(i - 2, 0), r1 = min(i + 2, Hh - 1);
                const int nrows = r1 - r0 + 1;
                const int nbr = max(0, min(r1, BW - 1) - r0 + 1)
                              + max(0, r1 - max(r0, Hh - BW) + 1);
                if (i < BW || i >= Hh - BW)
                    o = f4scale(NB, 1.0f / (float)(5 * nbr));
                else
                    o = f4scale(f4sub(S, NB), 1.0f / (float)(5 * (nrows - nbr)));
            }
            reinterpret_cast<float4*>(op + (size_t)i * Ww + (cb + 4))[0] = o;
            acc = f4sub(S, h[b]);                    // drop row i-2
        }
    }
}

// ===================== frame kernel: cols 0..11 and 1428..1439 ================
__global__ __launch_bounds__(256)
void seg_frame(const float* __restrict__ x, float* __restrict__ out)
{
    const int plane = blockIdx.y;
    const int half  = blockIdx.x;                    // row halves 0/1
    const float* __restrict__ xp = x   + (size_t)plane * (Hh * Ww);
    float* __restrict__       op = out + (size_t)plane * (Hh * Ww);

    for (int idx = threadIdx.x; idx < 6 * (Hh / 2); idx += 256) {
        const int q  = idx % 6;
        const int i  = half * (Hh / 2) + idx / 6;
        const int gq = (q < 3) ? q : (q + 354);      // {0,1,2,357,358,359}
        const int cb = 4 * gq - 4;
        const bool Aok = (cb >= 0);
        const bool Cok = (cb + 11 < Ww);

        float m[8];
        #pragma unroll
        for (int c = 0; c < 8; ++c) {
            const int col = cb + 2 + c;
            m[c] = (col < BW || col >= Ww - BW) ? 1.0f : 0.0f;
        }

        float4 S  = make_float4(0.f, 0.f, 0.f, 0.f);
        float4 NB = make_float4(0.f, 0.f, 0.f, 0.f);
        #pragma unroll
        for (int k = 0; k < 5; ++k) {
            const int r = i - 2 + k;
            if ((unsigned)r < (unsigned)Hh) {
                const float* rowp = xp + (size_t)r * Ww;
                const float4 A = Aok ? reinterpret_cast<const float4*>(rowp + cb)[0]
                                     : make_float4(0.f, 0.f, 0.f, 0.f);
                const float4 B = reinterpret_cast<const float4*>(rowp + cb + 4)[0];
                const float4 C = Cok ? reinterpret_cast<const float4*>(rowp + cb + 8)[0]
                                     : make_float4(0.f, 0.f, 0.f, 0.f);
                const float4 h = hfrom(A, B, C);
                S = f4add(S, h);
                if (r < BW || r >= Hh - BW) {
                    NB = f4add(NB, h);
                } else {
                    const float w0 = A.z * m[0], w1 = A.w * m[1];
                    const float w2 = B.x * m[2], w3 = B.y * m[3];
                    const float w4 = B.z * m[4], w5 = B.w * m[5];
                    const float w6 = C.x * m[6], w7 = C.y * m[7];
                    float4 hb;
                    hb.x = ((w0 + w1) + (w2 + w3)) + w4;
                    hb.y = hb.x - w0 + w5;
                    hb.z = hb.y - w1 + w6;
                    hb.w = hb.z - w2 + w7;
                    NB = f4add(NB, hb);
                }
            }
        }
        const int r0 = max(i - 2, 0), r1 = min(i + 2, Hh - 1);
        const int nrows = r1 - r0 + 1;
        const int nbr = max(0, min(r1, BW - 1) - r0 + 1)
                      + max(0, r1 - max(r0, Hh - BW) + 1);
        const bool rowBi = (i < BW || i >= Hh - BW);
        const float sv[4]  = {S.x, S.y, S.z, S.w};
        const float nbv[4] = {NB.x, NB.y, NB.z, NB.w};
        float ov[4];
        #pragma unroll
        for (int c = 0; c < 4; ++c) {
            const int j  = cb + 4 + c;
            const int c0 = max(j - 2, 0), c1 = min(j + 2, Ww - 1);
            const int ncols = c1 - c0 + 1;
            const int nbc = max(0, min(c1, BW - 1) - c0 + 1)
                          + max(0, c1 - max(c0, Ww - BW) + 1);
            const int  cntB = nbr * ncols + (nrows - nbr) * nbc;
            const bool mb   = rowBi || (j < BW || j >= Ww - BW);
            const float num = mb ? nbv[c] : (sv[c] - nbv[c]);
            const int   cnt = mb ? cntB : (nrows * ncols - cntB);
            ov[c] = num / (float)cnt;
        }
        reinterpret_cast<float4*>(op + (size_t)i * Ww + (cb + 4))[0]
            = make_float4(ov[0], ov[1], ov[2], ov[3]);
    }
}

extern "C" void kernel_launch(void* const* d_in, const int* in_sizes, int n_in,
                              void* d_out, int out_size)
{
    const float* x = (const float*)d_in[0];
    float* out = (float*)d_out;
    const int planes = out_size / (Hh * Ww);     // 64

    dim3 gf(2, planes);                          // tiny frame kernel first
    seg_frame<<<gf, 256>>>(x, out);

    dim3 gp(3, Hh / RSTRIP, planes);             // 3 x 36 x 64 = 6912 blocks
    seg_pure<<<gp, 128>>>(x, out);
}

// round 4
// speedup vs baseline: 2.0223x; 1.0670x over previous
#include <cuda_runtime.h>

#define Hh 720
#define Ww 1440
#define BW 10
#define RSTRIP 40          // output rows per strip (720 = 18 * 40)

__device__ __forceinline__ float4 f4add(const float4 a, const float4 b) {
    return make_float4(a.x + b.x, a.y + b.y, a.z + b.z, a.w + b.w);
}
__device__ __forceinline__ float4 f4sub(const float4 a, const float4 b) {
    return make_float4(a.x - b.x, a.y - b.y, a.z - b.z, a.w - b.w);
}
__device__ __forceinline__ float4 f4scale(const float4 a, const float s) {
    return make_float4(a.x * s, a.y * s, a.z * s, a.w * s);
}

__device__ __forceinline__ void stcs4(float* p, const float4 v) {
    asm volatile("st.global.cs.v4.f32 [%0], {%1,%2,%3,%4};"
                 :: "l"(p), "f"(v.x), "f"(v.y), "f"(v.z), "f"(v.w) : "memory");
}

// Load 3 aligned float4 covering cols cb..cb+11 of row r (zero-fill OOB rows).
__device__ __forceinline__ void loadraw(const float* __restrict__ xp, int r, int cb,
                                        float4& A, float4& B, float4& C)
{
    if ((unsigned)r < (unsigned)Hh) {
        const float4* p = reinterpret_cast<const float4*>(xp + (size_t)r * Ww + cb);
        A = p[0]; B = p[1]; C = p[2];
    } else {
        A = B = C = make_float4(0.f, 0.f, 0.f, 0.f);
    }
}

__device__ __forceinline__ float4 hfrom(const float4 A, const float4 B, const float4 C)
{
    float4 h;
    h.x = ((A.z + A.w) + (B.x + B.y)) + B.z;
    h.y = h.x - A.z + B.w;
    h.z = h.y - A.w + C.x;
    h.w = h.z - B.x + C.y;
    return h;
}

__global__ __launch_bounds__(128, 8)
void seg_smooth(const float* __restrict__ x, float* __restrict__ out)
{
    const int tid   = threadIdx.x;
    const int gi0   = blockIdx.y * RSTRIP;
    const int plane = blockIdx.z;
    const float* __restrict__ xp = x   + (size_t)plane * (Hh * Ww);
    float* __restrict__       op = out + (size_t)plane * (Hh * Ww);

    if (blockIdx.x < 3) {
        // ================= pure columns 12..1427 (rolling register ring) =====
        const int g = blockIdx.x * 128 + tid;
        if (g < 3 || g > 356) return;
        const int cb = 4 * g - 4;

        float4 h[5];
        {
            float4 A, B, C;
            loadraw(xp, gi0 - 2, cb, A, B, C); h[0] = hfrom(A, B, C);
            loadraw(xp, gi0 - 1, cb, A, B, C); h[1] = hfrom(A, B, C);
            loadraw(xp, gi0    , cb, A, B, C); h[2] = hfrom(A, B, C);
            loadraw(xp, gi0 + 1, cb, A, B, C); h[3] = hfrom(A, B, C);
        }
        float4 acc = f4add(f4add(h[0], h[1]), f4add(h[2], h[3]));

        float4 A, B, C;                              // prefetched row i+2
        loadraw(xp, gi0 + 2, cb, A, B, C);

        #pragma unroll 1
        for (int a = 0; a < RSTRIP / 5; ++a) {
            #pragma unroll
            for (int b = 0; b < 5; ++b) {
                const int i = gi0 + a * 5 + b;

                const float4 hn = hfrom(A, B, C);
                loadraw(xp, i + 3, cb, A, B, C);     // prefetch next row

                const int sn = (b + 4) % 5;
                h[sn] = hn;
                const float4 S = f4add(acc, hn);

                float4 o;
                if (i >= BW + 2 && i < Hh - BW - 2) {
                    o = f4scale(S, 0.04f);
                } else {
                    float4 NB = make_float4(0.f, 0.f, 0.f, 0.f);
                    #pragma unroll
                    for (int k = 0; k < 5; ++k) {
                        const int rk = i - 2 + k;    // OOB rows: h == 0
                        if (rk < BW || rk >= Hh - BW)
                            NB = f4add(NB, h[(b + k) % 5]);
                    }
                    const int r0 = max(i - 2, 0), r1 = min(i + 2, Hh - 1);
                    const int nrows = r1 - r0 + 1;
                    const int nbr = max(0, min(r1, BW - 1) - r0 + 1)
                                  + max(0, r1 - max(r0, Hh - BW) + 1);
                    if (i < BW || i >= Hh - BW)
                        o = f4scale(NB, 1.0f / (float)(5 * nbr));
                    else
                        o = f4scale(f4sub(S, NB), 1.0f / (float)(5 * (nrows - nbr)));
                }
                stcs4(op + (size_t)i * Ww + (cb + 4), o);
                acc = f4sub(S, h[b]);                // drop row i-2
            }
        }
    } else {
        // ================= frame columns 0..11 and 1428..1439 ================
        // 6 column groups x RSTRIP rows per block, one float4 output per item.
        for (int idx = tid; idx < 6 * RSTRIP; idx += 128) {
            const int q  = idx % 6;
            const int i  = gi0 + idx / 6;
            const int gq = (q < 3) ? q : (q + 354);  // {0,1,2,357,358,359}
            const int cb = 4 * gq - 4;
            const bool Aok = (cb >= 0);
            const bool Cok = (cb + 11 < Ww);

            float m[8];
            #pragma unroll
            for (int c = 0; c < 8; ++c) {
                const int col = cb + 2 + c;
                m[c] = (col < BW || col >= Ww - BW) ? 1.0f : 0.0f;
            }

            float4 S  = make_float4(0.f, 0.f, 0.f, 0.f);
            float4 NB = make_float4(0.f, 0.f, 0.f, 0.f);
            #pragma unroll
            for (int k = 0; k < 5; ++k) {
                const int r = i - 2 + k;
                if ((unsigned)r < (unsigned)Hh) {
                    const float* rowp = xp + (size_t)r * Ww;
                    const float4 A = Aok ? reinterpret_cast<const float4*>(rowp + cb)[0]
                                         : make_float4(0.f, 0.f, 0.f, 0.f);
                    const float4 B = reinterpret_cast<const float4*>(rowp + cb + 4)[0];
                    const float4 C = Cok ? reinterpret_cast<const float4*>(rowp + cb + 8)[0]
                                         : make_float4(0.f, 0.f, 0.f, 0.f);
                    const float4 h = hfrom(A, B, C);
                    S = f4add(S, h);
                    if (r < BW || r >= Hh - BW) {
                        NB = f4add(NB, h);
                    } else {
                        const float w0 = A.z * m[0], w1 = A.w * m[1];
                        const float w2 = B.x * m[2], w3 = B.y * m[3];
                        const float w4 = B.z * m[4], w5 = B.w * m[5];
                        const float w6 = C.x * m[6], w7 = C.y * m[7];
                        float4 hb;
                        hb.x = ((w0 + w1) + (w2 + w3)) + w4;
                        hb.y = hb.x - w0 + w5;
                        hb.z = hb.y - w1 + w6;
                        hb.w = hb.z - w2 + w7;
                        NB = f4add(NB, hb);
                    }
                }
            }
            const int r0 = max(i - 2, 0), r1 = min(i + 2, Hh - 1);
            const int nrows = r1 - r0 + 1;
            const int nbr = max(0, min(r1, BW - 1) - r0 + 1)
                          + max(0, r1 - max(r0, Hh - BW) + 1);
            const bool rowBi = (i < BW || i >= Hh - BW);
            const float sv[4]  = {S.x, S.y, S.z, S.w};
            const float nbv[4] = {NB.x, NB.y, NB.z, NB.w};
            float ov[4];
            #pragma unroll
            for (int c = 0; c < 4; ++c) {
                const int j  = cb + 4 + c;
                const int c0 = max(j - 2, 0), c1 = min(j + 2, Ww - 1);
                const int ncols = c1 - c0 + 1;
                const int nbc = max(0, min(c1, BW - 1) - c0 + 1)
                              + max(0, c1 - max(c0, Ww - BW) + 1);
                const int  cntB = nbr * ncols + (nrows - nbr) * nbc;
                const bool mb   = rowBi || (j < BW || j >= Ww - BW);
                const float num = mb ? nbv[c] : (sv[c] - nbv[c]);
                const int   cnt = mb ? cntB : (nrows * ncols - cntB);
                ov[c] = num / (float)cnt;
            }
            stcs4(op + (size_t)i * Ww + (cb + 4),
                  make_float4(ov[0], ov[1], ov[2], ov[3]));
        }
    }
}

extern "C" void kernel_launch(void* const* d_in, const int* in_sizes, int n_in,
                              void* d_out, int out_size)
{
    const float* x = (const float*)d_in[0];
    float* out = (float*)d_out;
    const int planes = out_size / (Hh * Ww);     // 64
    dim3 grid(4, Hh / RSTRIP, planes);           // 4 x 18 x 64 = 4608 blocks
    seg_smooth<<<grid, 128>>>(x, out);
}